// round 14
// baseline (speedup 1.0000x reference)
#include <cuda_runtime.h>
#include <cuda_bf16.h>
#include <cstdint>

#define NN 10000   // nodes
#define NE 160000  // edges
#define NB 4096    // batch
#define DD 512
#define HH 256
#define NCHUNK 8   // column chunks (512 cols each) for fused logits+lse

// ---------------- scratch (device globals; no runtime alloc) ----------------
__device__ __nv_bfloat16 g_ia[NB * DD];
__device__ __nv_bfloat16 g_wg1t[HH * DD];
__device__ __nv_bfloat16 g_wg2t[DD * HH];
__device__ __nv_bfloat16 g_wi1t[HH * DD];
__device__ __nv_bfloat16 g_wi2t[DD * HH];
__device__ __nv_bfloat16 g_xw1[NN * HH];     // layer-1 xw
__device__ __nv_bfloat16 g_h[NN * HH];       // layer-1 output (all nodes)
__device__ __nv_bfloat16 g_aggl[NB * HH];    // agg(h) at label rows
__device__ __nv_bfloat16 g_gcn[NB * DD];     // gcn at label rows (batch-ordered)
__device__ __nv_bfloat16 g_t1[NB * HH];
__device__ __nv_bfloat16 g_img[NB * DD];
__device__ float g_pm[NCHUNK * NB];
__device__ float g_ps[NCHUNK * NB];
__device__ float g_diag[NB];
__device__ float g_part[32];
__device__ float g_dinv[NN];
__device__ int   g_counts[NN];
__device__ int   g_offsets[NN];
__device__ int   g_cursor[NN];
__device__ int   g_srcs[NE];
__device__ float g_wts[NE];

// ---------------- graph preprocessing ----------------
__global__ void k_count(const int* __restrict__ ei) {
    int e = blockIdx.x * blockDim.x + threadIdx.x;
    if (e < NE) atomicAdd(&g_counts[ei[NE + e]], 1);
}

__global__ void k_scan() {
    __shared__ int wsum[32];
    const int CH = 10;
    int t = threadIdx.x;
    int lane = t & 31, warp = t >> 5;
    int base = t * CH;
    int loc[CH];
    int sum = 0;
#pragma unroll
    for (int j = 0; j < CH; j++) {
        int idx = base + j;
        int c = (idx < NN) ? g_counts[idx] : 0;
        loc[j] = c; sum += c;
        if (idx < NN) g_dinv[idx] = rsqrtf(1.0f + (float)c);
    }
    int inc = sum;
#pragma unroll
    for (int off = 1; off < 32; off <<= 1) {
        int v = __shfl_up_sync(0xffffffffu, inc, off);
        if (lane >= off) inc += v;
    }
    if (lane == 31) wsum[warp] = inc;
    __syncthreads();
    if (warp == 0) {
        int v = wsum[lane];
        int wi = v;
#pragma unroll
        for (int off = 1; off < 32; off <<= 1) {
            int u = __shfl_up_sync(0xffffffffu, wi, off);
            if (lane >= off) wi += u;
        }
        wsum[lane] = wi - v;
    }
    __syncthreads();
    int run = wsum[warp] + (inc - sum);
#pragma unroll
    for (int j = 0; j < CH; j++) {
        int idx = base + j;
        if (idx < NN) g_offsets[idx] = run;
        run += loc[j];
    }
}

__global__ void k_fill(const int* __restrict__ ei) {
    int e = blockIdx.x * blockDim.x + threadIdx.x;
    if (e < NE) {
        int s = ei[e], d = ei[NE + e];
        int pos = g_offsets[d] + atomicAdd(&g_cursor[d], 1);
        g_srcs[pos] = s;
        g_wts[pos] = g_dinv[s] * g_dinv[d];
    }
}

// ---------------- fp32 -> bf16 convert ----------------
__global__ void k_conv(const float* __restrict__ in, __nv_bfloat16* __restrict__ out, int n) {
    int i4 = (blockIdx.x * blockDim.x + threadIdx.x) * 4;
    if (i4 >= n) return;
    float4 v = *(const float4*)(in + i4);
    out[i4 + 0] = __float2bfloat16_rn(v.x);
    out[i4 + 1] = __float2bfloat16_rn(v.y);
    out[i4 + 2] = __float2bfloat16_rn(v.z);
    out[i4 + 3] = __float2bfloat16_rn(v.w);
}

// single weight transpose: W [K][N] fp32 -> Wt [N][K] bf16 (W_g1: K=512,N=256)
__global__ void k_convT1(const float* __restrict__ W, __nv_bfloat16* __restrict__ Wt) {
    __shared__ float tile[32][33];
    int lb = blockIdx.x;                      // 128 blocks
    int n0 = (lb % (HH / 32)) * 32, k0 = (lb / (HH / 32)) * 32;
    tile[threadIdx.y][threadIdx.x] = W[(size_t)(k0 + threadIdx.y) * HH + n0 + threadIdx.x];
    __syncthreads();
    Wt[(size_t)(n0 + threadIdx.y) * DD + k0 + threadIdx.x] =
        __float2bfloat16_rn(tile[threadIdx.x][threadIdx.y]);
}

// 3 weight transposes in one launch (W_g2, W_img1, W_img2)
__global__ void k_convT3(const float* __restrict__ w2, __nv_bfloat16* __restrict__ o2,
                         const float* __restrict__ w3, __nv_bfloat16* __restrict__ o3,
                         const float* __restrict__ w4, __nv_bfloat16* __restrict__ o4) {
    __shared__ float tile[32][33];
    int b = blockIdx.x;
    const float* W;
    __nv_bfloat16* Wt;
    int K, N, lb;
    if (b < 128)      { W = w2; Wt = o2; K = HH; N = DD; lb = b; }
    else if (b < 256) { W = w3; Wt = o3; K = DD; N = HH; lb = b - 128; }
    else              { W = w4; Wt = o4; K = HH; N = DD; lb = b - 256; }
    int nx = N / 32;
    int n0 = (lb % nx) * 32, k0 = (lb / nx) * 32;
    tile[threadIdx.y][threadIdx.x] = W[(size_t)(k0 + threadIdx.y) * N + n0 + threadIdx.x];
    __syncthreads();
    Wt[(size_t)(n0 + threadIdx.y) * K + k0 + threadIdx.x] =
        __float2bfloat16_rn(tile[threadIdx.x][threadIdx.y]);
}

// ------- GCN aggregation: warp-per-edge, uint4 gathers, smem reduce --------
template <bool RELU, bool BIAS>
__global__ void k_aggw(const __nv_bfloat16* __restrict__ xw, const float* __restrict__ bias,
                       __nv_bfloat16* __restrict__ out, const int* __restrict__ IDX) {
    __shared__ float red[8][256];
    int v = IDX ? IDX[blockIdx.x] : blockIdx.x;
    int warp = threadIdx.x >> 5, lane = threadIdx.x & 31;
    int rs = g_offsets[v], cnt = g_counts[v];
    float acc[8] = {0.f, 0.f, 0.f, 0.f, 0.f, 0.f, 0.f, 0.f};
    for (int i = warp; i < cnt; i += 8) {
        int s = g_srcs[rs + i];
        float w = g_wts[rs + i];
        uint4 d = *(const uint4*)(xw + (size_t)s * 256 + lane * 8);
        const __nv_bfloat162* p = (const __nv_bfloat162*)&d;
#pragma unroll
        for (int j = 0; j < 4; j++) {
            float2 f = __bfloat1622float2(p[j]);
            acc[2 * j]     += w * f.x;
            acc[2 * j + 1] += w * f.y;
        }
    }
#pragma unroll
    for (int j = 0; j < 8; j++) red[warp][lane * 8 + j] = acc[j];
    __syncthreads();
    int f = threadIdx.x;
    float dv = g_dinv[v];
    float a = dv * dv * __bfloat162float(xw[(size_t)v * 256 + f]);
#pragma unroll
    for (int w2 = 0; w2 < 8; w2++) a += red[w2][f];
    if (BIAS) a += bias[f];
    out[(size_t)blockIdx.x * 256 + f] = __float2bfloat16_rn(RELU ? fmaxf(a, 0.f) : a);
}

// ---------------- cp.async / ldmatrix helpers ----------------
__device__ __forceinline__ void cp16(uint32_t smem, const void* gmem, int srcBytes) {
    asm volatile("cp.async.cg.shared.global [%0], [%1], 16, %2;"
                 :: "r"(smem), "l"(gmem), "r"(srcBytes));
}
__device__ __forceinline__ void cp_commit() { asm volatile("cp.async.commit_group;"); }
template <int N>
__device__ __forceinline__ void cp_wait() { asm volatile("cp.async.wait_group %0;" :: "n"(N)); }

__device__ __forceinline__ void ldsm4(uint32_t& r0, uint32_t& r1, uint32_t& r2, uint32_t& r3,
                                      uint32_t addr) {
    asm volatile("ldmatrix.sync.aligned.m8n8.x4.shared.b16 {%0,%1,%2,%3}, [%4];"
                 : "=r"(r0), "=r"(r1), "=r"(r2), "=r"(r3) : "r"(addr));
}

__device__ __forceinline__ uint32_t smem_u32(const void* p) {
    uint32_t a;
    asm("{ .reg .u64 t; cvta.to.shared.u64 t, %1; cvt.u32.u64 %0, t; }" : "=r"(a) : "l"(p));
    return a;
}

#define SSTR 40  // smem row stride in bf16 elems (80B, ldmatrix-aligned, conflict-free)
#define STGB (128 * SSTR * 2)

#define MMA(acc, a0, a1, a2, a3, b0, b1)                                     \
    asm volatile(                                                            \
        "mma.sync.aligned.m16n8k16.row.col.f32.bf16.bf16.f32 "               \
        "{%0,%1,%2,%3}, {%4,%5,%6,%7}, {%8,%9}, {%0,%1,%2,%3};"              \
        : "+f"((acc)[0]), "+f"((acc)[1]), "+f"((acc)[2]), "+f"((acc)[3])     \
        : "r"(a0), "r"(a1), "r"(a2), "r"(a3), "r"(b0), "r"(b1))

// 64x32 warp tile from one 128x32 As/Bs stage
__device__ __forceinline__ void mma_tile(uint32_t sAs, uint32_t sBs,
                                         int wm, int wn, int lane,
                                         float acc[4][4][4]) {
    const int aRow = (lane & 7) + ((lane >> 3) & 1) * 8;
    const int aCol = (lane >> 4) * 8;
    const int bRow = (lane & 7) + (lane >> 4) * 8;
    const int bCol = ((lane >> 3) & 1) * 8;
#pragma unroll
    for (int kk = 0; kk < 32; kk += 16) {
        uint32_t af[4][4], bf[4][2];
#pragma unroll
        for (int mi = 0; mi < 4; mi++) {
            uint32_t a = sAs + ((wm + mi * 16 + aRow) * SSTR + kk + aCol) * 2;
            ldsm4(af[mi][0], af[mi][1], af[mi][2], af[mi][3], a);
        }
#pragma unroll
        for (int p = 0; p < 2; p++) {
            uint32_t b = sBs + ((wn + p * 16 + bRow) * SSTR + kk + bCol) * 2;
            ldsm4(bf[2 * p][0], bf[2 * p][1], bf[2 * p + 1][0], bf[2 * p + 1][1], b);
        }
#pragma unroll
        for (int mi = 0; mi < 4; mi++)
#pragma unroll
            for (int ni = 0; ni < 4; ni++)
                MMA(acc[mi][ni], af[mi][0], af[mi][1], af[mi][2], af[mi][3],
                    bf[ni][0], bf[ni][1]);
    }
}

#define GEMM_MAINLOOP(nK, ISSUE)                                             \
    ISSUE(0, 0); cp_commit();                                                \
    ISSUE(32, 1); cp_commit();                                               \
    for (int i = 0; i < (nK); i++) {                                         \
        cp_wait<1>();                                                        \
        __syncthreads();                                                     \
        if (i + 2 < (nK)) { ISSUE((i + 2) * 32, (i + 2) % 3); }              \
        cp_commit();                                                         \
        mma_tile(sAbase + ((i % 3) * STGB), sBbase + ((i % 3) * STGB),       \
                 wm, wn, lane, acc);                                         \
    }

// ---------------- bf16 NT GEMM (mma.sync), 3-stage cp.async ---------------
template <bool RELU, bool BIAS>
__global__ void bgemm(int M, int N, int K,
                      const __nv_bfloat16* __restrict__ A,
                      const __nv_bfloat16* __restrict__ B,
                      __nv_bfloat16* __restrict__ C,
                      const float* __restrict__ bias) {
    __shared__ __align__(16) __nv_bfloat16 As[3][128 * SSTR];
    __shared__ __align__(16) __nv_bfloat16 Bs[3][128 * SSTR];
    const int tid = threadIdx.x;
    const int lane = tid & 31, warp = tid >> 5;
    const int wm = (warp & 1) * 64, wn = (warp >> 1) * 32;
    const int g = lane >> 2, tg = lane & 3;
    const int brow = blockIdx.y * 128, bcol = blockIdx.x * 128;

    float acc[4][4][4];
#pragma unroll
    for (int a = 0; a < 4; a++)
#pragma unroll
        for (int b = 0; b < 4; b++)
#pragma unroll
            for (int c = 0; c < 4; c++) acc[a][b][c] = 0.f;

    const int lrow = tid >> 1;
    const int lk = (tid & 1) * 16;
    int arow = brow + lrow;
    bool aval = arow < M;
    int aSrc = aval ? 16 : 0;
    const __nv_bfloat16* Ap = A + (long)(aval ? arow : 0) * K + lk;
    const __nv_bfloat16* Bp = B + (long)(bcol + lrow) * K + lk;

    uint32_t sAbase = smem_u32(&As[0][0]);
    uint32_t sBbase = smem_u32(&Bs[0][0]);
    uint32_t sA = sAbase + (lrow * SSTR + lk) * 2;
    uint32_t sB = sBbase + (lrow * SSTR + lk) * 2;

    const int nK = K / 32;
#define ISSUE_G(k0, slot)                                                    \
    cp16(sA + (slot) * STGB, Ap + (k0), aSrc);                               \
    cp16(sA + (slot) * STGB + 16, Ap + (k0) + 8, aSrc);                      \
    cp16(sB + (slot) * STGB, Bp + (k0), 16);                                 \
    cp16(sB + (slot) * STGB + 16, Bp + (k0) + 8, 16);
    GEMM_MAINLOOP(nK, ISSUE_G)
#undef ISSUE_G

#pragma unroll
    for (int mi = 0; mi < 4; mi++) {
#pragma unroll
        for (int half = 0; half < 2; half++) {
            int r = brow + wm + mi * 16 + g + half * 8;
            if (r >= M) continue;
#pragma unroll
            for (int ni = 0; ni < 4; ni++) {
                int c = bcol + wn + ni * 8 + tg * 2;
                float v0 = acc[mi][ni][half * 2 + 0];
                float v1 = acc[mi][ni][half * 2 + 1];
                if (BIAS) { v0 += bias[c]; v1 += bias[c + 1]; }
                if (RELU) { v0 = fmaxf(v0, 0.f); v1 = fmaxf(v1, 0.f); }
                __nv_bfloat162 h;
                h.x = __float2bfloat16_rn(v0);
                h.y = __float2bfloat16_rn(v1);
                *(__nv_bfloat162*)(C + (size_t)r * N + c) = h;
            }
        }
    }
}

// ------ L1 GEMM with fused fp32->bf16 A conversion (N=256, K=512) ----------
// A fp32 via register-staged LDG (2-slot smem); B via 3-slot cp.async ring
// with wait<1> (one group always in flight).
__global__ void bgemm_convA(int M, const float* __restrict__ Af,
                            const __nv_bfloat16* __restrict__ B,
                            __nv_bfloat16* __restrict__ C) {
    __shared__ __align__(16) __nv_bfloat16 As[2][128 * SSTR];
    __shared__ __align__(16) __nv_bfloat16 Bs[3][128 * SSTR];
    const int tid = threadIdx.x;
    const int lane = tid & 31, warp = tid >> 5;
    const int wm = (warp & 1) * 64, wn = (warp >> 1) * 32;
    const int g = lane >> 2, tg = lane & 3;
    const int brow = blockIdx.y * 128, bcol = blockIdx.x * 128;

    float acc[4][4][4];
#pragma unroll
    for (int a = 0; a < 4; a++)
#pragma unroll
        for (int b = 0; b < 4; b++)
#pragma unroll
            for (int c = 0; c < 4; c++) acc[a][b][c] = 0.f;

    const int lrow = tid >> 1;
    const int lk = (tid & 1) * 16;
    int arow = brow + lrow;
    bool aval = arow < M;
    const float* Ap = Af + (long)(aval ? arow : 0) * DD + lk;
    const __nv_bfloat16* Bp = B + (long)(bcol + lrow) * DD + lk;

    uint32_t sAbase = smem_u32(&As[0][0]);
    uint32_t sBbase = smem_u32(&Bs[0][0]);
    uint32_t sB = sBbase + (lrow * SSTR + lk) * 2;

    float4 a4[4];
#define LDA(k0)                                                              \
    if (aval) {                                                              \
        a4[0] = *(const float4*)(Ap + (k0));                                 \
        a4[1] = *(const float4*)(Ap + (k0) + 4);                             \
        a4[2] = *(const float4*)(Ap + (k0) + 8);                             \
        a4[3] = *(const float4*)(Ap + (k0) + 12);                            \
    } else {                                                                 \
        a4[0] = a4[1] = a4[2] = a4[3] = make_float4(0.f, 0.f, 0.f, 0.f);     \
    }
#define STA(slot)                                                            \
    {                                                                        \
        uint4 u0, u1;                                                        \
        __nv_bfloat162* q0 = (__nv_bfloat162*)&u0;                           \
        __nv_bfloat162* q1 = (__nv_bfloat162*)&u1;                           \
        q0[0] = __float22bfloat162_rn(make_float2(a4[0].x, a4[0].y));        \
        q0[1] = __float22bfloat162_rn(make_float2(a4[0].z, a4[0].w));        \
        q0[2] = __float22bfloat162_rn(make_float2(a4[1].x, a4[1].y));        \
        q0[3] = __float22bfloat162_rn(make_float2(a4[1].z, a4[1].w));        \
        q1[0] = __float22bfloat162_rn(make_float2(a4[2].x, a4[2].y));        \
        q1[1] = __float22bfloat162_rn(make_float2(a4[2].z, a4[2].w));        \
        q1[2] = __float22bfloat162_rn(make_float2(a4[3].x, a4[3].y));        \
        q1[3] = __float22bfloat162_rn(make_float2(a4[3].z, a4[3].w));        \
        *(uint4*)&As[slot][lrow * SSTR + lk] = u0;                           \
        *(uint4*)&As[slot][lrow * SSTR + lk + 8] = u1;                       \
    }
#define LDB(k0, slot)                                                        \
    cp16(sB + (slot) * STGB, Bp + (k0), 16);                                 \
    cp16(sB + (slot) * STGB + 16, Bp + (k0) + 8, 16);

    const int nK = DD / 32;  // 16
    // prologue: A0 -> smem slot0; A1 -> regs; B0,B1 in flight (2 groups)
    LDA(0);
    STA(0);
    LDA(32);
    LDB(0, 0); cp_commit();
    LDB(32, 1); cp_commit();

    for (int i = 0; i < nK; i++) {
        cp_wait<1>();       // B(i) landed; B(i+1) may still be in flight
        __syncthreads();    // + all mma(i-1) reads complete (A slot & B slot reuse safe)
        if (i + 1 < nK) {
            STA((i + 1) & 1);                       // A(i+1) regs -> smem
            if (i + 2 < nK) {
                LDA((i + 2) * 32);                  // prefetch A(i+2) to regs
                LDB((i + 2) * 32, (i + 2) % 3);     // B(i+2): slot last read at i-1
            }
        }
        cp_commit();
        mma_tile(sAbase + (i & 1) * STGB, sBbase + (i % 3) * STGB,
                 wm, wn, lane, acc);
    }
#undef LDA
#undef STA
#undef LDB

#pragma unroll
    for (int mi = 0; mi < 4; mi++) {
#pragma unroll
        for (int half = 0; half < 2; half++) {
            int r = brow + wm + mi * 16 + g + half * 8;
            if (r >= M) continue;
#pragma unroll
            for (int ni = 0; ni < 4; ni++) {
                int c = bcol + wn + ni * 8 + tg * 2;
                __nv_bfloat162 h;
                h.x = __float2bfloat16_rn(acc[mi][ni][half * 2 + 0]);
                h.y = __float2bfloat16_rn(acc[mi][ni][half * 2 + 1]);
                *(__nv_bfloat162*)(C + (size_t)r * HH + c) = h;
            }
        }
    }
}

// ------- fused logits GEMM + online row LSE + diag (R11 per-tile pipeline) --
__global__ void k_logits_lse(const __nv_bfloat16* __restrict__ A,   // gcn_lbl [NB][DD]
                             const __nv_bfloat16* __restrict__ B) { // img [NB][DD]
    __shared__ __align__(16) __nv_bfloat16 As[3][128 * SSTR];
    __shared__ __align__(16) __nv_bfloat16 Bs[3][128 * SSTR];
    __shared__ float red_m[4][128];
    __shared__ float red_s[4][128];

    const int tid = threadIdx.x;
    const int lane = tid & 31, warp = tid >> 5;
    const int wm = (warp & 1) * 64, wn = (warp >> 1) * 32;
    const int wnIdx = warp >> 1;
    const int g = lane >> 2, tg = lane & 3;
    const int brow = blockIdx.y * 128;
    const int chunk = blockIdx.x;

    const int lrow = tid >> 1;
    const int lk = (tid & 1) * 16;
    const __nv_bfloat16* Ap = A + (long)(brow + lrow) * DD + lk;

    uint32_t sAbase = smem_u32(&As[0][0]);
    uint32_t sBbase = smem_u32(&Bs[0][0]);
    uint32_t sA = sAbase + (lrow * SSTR + lk) * 2;
    uint32_t sB = sBbase + (lrow * SSTR + lk) * 2;

    float run_m = -3.0e38f, run_s = 0.f;  // valid for tid < 128 (row = tid)

    for (int nt = 0; nt < 4; nt++) {
        const int bcol = chunk * 512 + nt * 128;
        const __nv_bfloat16* Bp = B + (long)(bcol + lrow) * DD + lk;

        float acc[4][4][4];
#pragma unroll
        for (int a = 0; a < 4; a++)
#pragma unroll
            for (int b = 0; b < 4; b++)
#pragma unroll
                for (int c = 0; c < 4; c++) acc[a][b][c] = 0.f;

        const int nK = DD / 32;  // 16
#define ISSUE_L(k0, slot)                                                    \
    cp16(sA + (slot) * STGB, Ap + (k0), 16);                                 \
    cp16(sA + (slot) * STGB + 16, Ap + (k0) + 8, 16);                        \
    cp16(sB + (slot) * STGB, Bp + (k0), 16);                                 \
    cp16(sB + (slot) * STGB + 16, Bp + (k0) + 8, 16);
        GEMM_MAINLOOP(nK, ISSUE_L)
#undef ISSUE_L
        __syncthreads();  // mainloop reads done; also fences red_* reuse

        // ---- per warp-column local (max, sumexp) + diag, one smem round ----
#pragma unroll
        for (int mi = 0; mi < 4; mi++) {
#pragma unroll
            for (int half = 0; half < 2; half++) {
                int row = wm + mi * 16 + g + half * 8;
                float v = -3.0e38f;
#pragma unroll
                for (int ni = 0; ni < 4; ni++)
                    v = fmaxf(v, fmaxf(acc[mi][ni][half * 2], acc[mi][ni][half * 2 + 1]));
                v = fmaxf(v, __shfl_xor_sync(0xffffffffu, v, 1));
                v = fmaxf(v, __shfl_xor_sync(0xffffffffu, v, 2));
                float ps = 0.f;
#pragma unroll
                for (int ni = 0; ni < 4; ni++) {
#pragma unroll
                    for (int j = 0; j < 2; j++) {
                        float x = acc[mi][ni][half * 2 + j];
                        ps += __expf(x - v);
                        int gc = bcol + wn + ni * 8 + tg * 2 + j;
                        if (gc == brow + row) g_diag[gc] = x;
                    }
                }
                ps += __shfl_xor_sync(0xffffffffu, ps, 1);
                ps += __shfl_xor_sync(0xffffffffu, ps, 2);
                if (tg == 0) { red_m[wnIdx][row] = v; red_s[wnIdx][row] = ps; }
            }
        }
        __syncthreads();
        if (tid < 128) {
            float m0 = red_m[0][tid], m1 = red_m[1][tid];
            float m2 = red_m[2][tid], m3 = red_m[3][tid];
            float M = fmaxf(fmaxf(m0, m1), fmaxf(m2, m3));
            float S = red_s[0][tid] * __expf(m0 - M) + red_s[1][tid] * __expf(m1 - M)
                    + red_s[2][tid] * __expf(m2 - M) + red_s[3][tid] * __expf(m3 - M);
            float nm = fmaxf(run_m, M);
            run_s = run_s * __expf(run_m - nm) + S * __expf(M - nm);
            run_m = nm;
        }
        // no extra sync: next tile's mainloop syncs before red_* is rewritten
    }

    if (tid < 128) {
        g_pm[chunk * NB + brow + tid] = run_m;
        g_ps[chunk * NB + brow + tid] = run_s;
    }
}

// ---------- merge partials: stage 1 (32 blocks x 128 rows) ----------
__global__ void k_merge(const int* __restrict__ label) {
    __shared__ float sh[128];
    int i = blockIdx.x * 128 + threadIdx.x;
    float m = -3.0e38f;
#pragma unroll
    for (int c = 0; c < NCHUNK; c++) m = fmaxf(m, g_pm[c * NB + i]);
    float s = 0.f;
#pragma unroll
    for (int c = 0; c < NCHUNK; c++) s += g_ps[c * NB + i] * __expf(g_pm[c * NB + i] - m);
    float lse = m + logf(s);
    sh[threadIdx.x] = -(float)label[i] * (g_diag[i] - lse);
    __syncthreads();
    for (int off = 64; off > 0; off >>= 1) {
        if (threadIdx.x < off) sh[threadIdx.x] += sh[threadIdx.x + off];
        __syncthreads();
    }
    if (threadIdx.x == 0) g_part[blockIdx.x] = sh[0];
}

// ---------- stage 2: final scalar ----------
__global__ void k_final(float* __restrict__ out) {
    float v = g_part[threadIdx.x];  // 32 threads
#pragma unroll
    for (int off = 16; off > 0; off >>= 1)
        v += __shfl_xor_sync(0xffffffffu, v, off);
    if (threadIdx.x == 0) out[0] = v / (float)NB + 1.0f;  // + triplet (==1 exactly)
}

// ---------------- launch ----------------
extern "C" void kernel_launch(void* const* d_in, const int* in_sizes, int n_in,
                              void* d_out, int out_size) {
    const float* image  = (const float*)d_in[0];
    const float* xnodes = (const float*)d_in[1];
    const int*   ei     = (const int*)d_in[2];
    const int*   label  = (const int*)d_in[3];
    const float* W_img1 = (const float*)d_in[4];
    const float* b_img1 = (const float*)d_in[5];
    const float* W_img2 = (const float*)d_in[6];
    const float* b_img2 = (const float*)d_in[7];
    const float* W_g1   = (const float*)d_in[8];
    const float* b_g1   = (const float*)d_in[9];
    const float* W_g2   = (const float*)d_in[10];
    const float* b_g2   = (const float*)d_in[11];

    __nv_bfloat16 *p_ia, *p_wg1t, *p_wg2t, *p_wi1t, *p_wi2t;
    __nv_bfloat16 *p_xw1, *p_h, *p_aggl, *p_gcn, *p_t1, *p_img;
    int *p_counts, *p_cursor;
    cudaGetSymbolAddress((void**)&p_ia, g_ia);
    cudaGetSymbolAddress((void**)&p_wg1t, g_wg1t);
    cudaGetSymbolAddress((void**)&p_wg2t, g_wg2t);
    cudaGetSymbolAddress((void**)&p_wi1t, g_wi1t);
    cudaGetSymbolAddress((void**)&p_wi2t, g_wi2t);
    cudaGetSymbolAddress((void**)&p_xw1, g_xw1);
    cudaGetSymbolAddress((void**)&p_h, g_h);
    cudaGetSymbolAddress((void**)&p_aggl, g_aggl);
    cudaGetSymbolAddress((void**)&p_gcn, g_gcn);
    cudaGetSymbolAddress((void**)&p_t1, g_t1);
    cudaGetSymbolAddress((void**)&p_img, g_img);
    cudaGetSymbolAddress((void**)&p_counts, g_counts);
    cudaGetSymbolAddress((void**)&p_cursor, g_cursor);

    // one-time stream/event setup
    static cudaStream_t sCsr = nullptr, sMlp = nullptr;
    static cudaEvent_t evRoot, evCsr, evT3, evMlp;
    if (sCsr == nullptr) {
        cudaStreamCreateWithFlags(&sCsr, cudaStreamNonBlocking);
        cudaStreamCreateWithFlags(&sMlp, cudaStreamNonBlocking);
        cudaEventCreateWithFlags(&evRoot, cudaEventDisableTiming);
        cudaEventCreateWithFlags(&evCsr, cudaEventDisableTiming);
        cudaEventCreateWithFlags(&evT3, cudaEventDisableTiming);
        cudaEventCreateWithFlags(&evMlp, cudaEventDisableTiming);
    }

    // fork point
    cudaEventRecord(evRoot, 0);

    // ---- branch 1 (sCsr): CSR build ----
    cudaStreamWaitEvent(sCsr, evRoot, 0);
    cudaMemsetAsync(p_counts, 0, NN * sizeof(int), sCsr);
    cudaMemsetAsync(p_cursor, 0, NN * sizeof(int), sCsr);
    k_count<<<(NE + 255) / 256, 256, 0, sCsr>>>(ei);
    k_scan<<<1, 1024, 0, sCsr>>>();
    k_fill<<<(NE + 255) / 256, 256, 0, sCsr>>>(ei);
    cudaEventRecord(evCsr, sCsr);

    // ---- branch 2 (sMlp): other transposes + image convert + MLP ----
    cudaStreamWaitEvent(sMlp, evRoot, 0);
    k_convT3<<<384, dim3(32, 32), 0, sMlp>>>(W_g2, p_wg2t, W_img1, p_wi1t, W_img2, p_wi2t);
    cudaEventRecord(evT3, sMlp);
    k_conv<<<(NB * DD / 4 + 255) / 256, 256, 0, sMlp>>>(image, p_ia, NB * DD);
    {
        dim3 grid(HH / 128, NB / 128);
        bgemm<true, true><<<grid, 256, 0, sMlp>>>(NB, HH, DD, p_ia, p_wi1t, p_t1, b_img1);
    }
    {
        dim3 grid(DD / 128, NB / 128);
        bgemm<true, true><<<grid, 256, 0, sMlp>>>(NB, DD, HH, p_t1, p_wi2t, p_img, b_img2);
    }
    cudaEventRecord(evMlp, sMlp);

    // ---- main stream: W_g1 transpose only, then GCN chain ----
    k_convT1<<<128, dim3(32, 32)>>>(W_g1, p_wg1t);
    {
        dim3 grid(HH / 128, (NN + 127) / 128);
        bgemm_convA<<<grid, 256>>>(NN, xnodes, p_wg1t, p_xw1);
    }
    cudaStreamWaitEvent(0, evCsr, 0);
    k_aggw<true, true><<<NN, 256>>>(p_xw1, b_g1, p_h, nullptr);
    k_aggw<false, false><<<NB, 256>>>(p_h, nullptr, p_aggl, label);
    cudaStreamWaitEvent(0, evT3, 0);
    {
        dim3 grid(DD / 128, NB / 128);
        bgemm<false, true><<<grid, 256>>>(NB, DD, HH, p_aggl, p_wg2t, p_gcn, b_g2);
    }

    // ---- join MLP, then fused logits + LSE ----
    cudaStreamWaitEvent(0, evMlp, 0);
    {
        dim3 grid(NCHUNK, NB / 128);
        k_logits_lse<<<grid, 256>>>(p_gcn, p_img);
    }
    k_merge<<<32, 128>>>(label);
    k_final<<<1, 32>>>((float*)d_out);
}

// round 15
// speedup vs baseline: 1.0116x; 1.0116x over previous
#include <cuda_runtime.h>
#include <cuda_bf16.h>
#include <cstdint>

#define NN 10000   // nodes
#define NE 160000  // edges
#define NB 4096    // batch
#define DD 512
#define HH 256
#define NCHUNK 16  // column chunks (256 cols each) for fused logits+lse

// ---------------- scratch (device globals; no runtime alloc) ----------------
__device__ __nv_bfloat16 g_ia[NB * DD];
__device__ __nv_bfloat16 g_wg1t[HH * DD];
__device__ __nv_bfloat16 g_wg2t[DD * HH];
__device__ __nv_bfloat16 g_wi1t[HH * DD];
__device__ __nv_bfloat16 g_wi2t[DD * HH];
__device__ __nv_bfloat16 g_xw1[NN * HH];     // layer-1 xw
__device__ __nv_bfloat16 g_h[NN * HH];       // layer-1 output (all nodes)
__device__ __nv_bfloat16 g_aggl[NB * HH];    // agg(h) at label rows
__device__ __nv_bfloat16 g_gcn[NB * DD];     // gcn at label rows (batch-ordered)
__device__ __nv_bfloat16 g_t1[NB * HH];
__device__ __nv_bfloat16 g_img[NB * DD];
__device__ float g_pm[NCHUNK * NB];
__device__ float g_ps[NCHUNK * NB];
__device__ float g_diag[NB];
__device__ float g_part[32];
__device__ float g_dinv[NN];
__device__ int   g_counts[NN];
__device__ int   g_offsets[NN];
__device__ int   g_cursor[NN];
__device__ int   g_srcs[NE];
__device__ float g_wts[NE];

// ---------------- graph preprocessing ----------------
__global__ void k_count(const int* __restrict__ ei) {
    int e = blockIdx.x * blockDim.x + threadIdx.x;
    if (e < NE) atomicAdd(&g_counts[ei[NE + e]], 1);
}

__global__ void k_scan() {
    __shared__ int wsum[32];
    const int CH = 10;
    int t = threadIdx.x;
    int lane = t & 31, warp = t >> 5;
    int base = t * CH;
    int loc[CH];
    int sum = 0;
#pragma unroll
    for (int j = 0; j < CH; j++) {
        int idx = base + j;
        int c = (idx < NN) ? g_counts[idx] : 0;
        loc[j] = c; sum += c;
        if (idx < NN) g_dinv[idx] = rsqrtf(1.0f + (float)c);
    }
    int inc = sum;
#pragma unroll
    for (int off = 1; off < 32; off <<= 1) {
        int v = __shfl_up_sync(0xffffffffu, inc, off);
        if (lane >= off) inc += v;
    }
    if (lane == 31) wsum[warp] = inc;
    __syncthreads();
    if (warp == 0) {
        int v = wsum[lane];
        int wi = v;
#pragma unroll
        for (int off = 1; off < 32; off <<= 1) {
            int u = __shfl_up_sync(0xffffffffu, wi, off);
            if (lane >= off) wi += u;
        }
        wsum[lane] = wi - v;
    }
    __syncthreads();
    int run = wsum[warp] + (inc - sum);
#pragma unroll
    for (int j = 0; j < CH; j++) {
        int idx = base + j;
        if (idx < NN) g_offsets[idx] = run;
        run += loc[j];
    }
}

__global__ void k_fill(const int* __restrict__ ei) {
    int e = blockIdx.x * blockDim.x + threadIdx.x;
    if (e < NE) {
        int s = ei[e], d = ei[NE + e];
        int pos = g_offsets[d] + atomicAdd(&g_cursor[d], 1);
        g_srcs[pos] = s;
        g_wts[pos] = g_dinv[s] * g_dinv[d];
    }
}

// ---------------- fp32 -> bf16 convert ----------------
__global__ void k_conv(const float* __restrict__ in, __nv_bfloat16* __restrict__ out, int n) {
    int i4 = (blockIdx.x * blockDim.x + threadIdx.x) * 4;
    if (i4 >= n) return;
    float4 v = *(const float4*)(in + i4);
    out[i4 + 0] = __float2bfloat16_rn(v.x);
    out[i4 + 1] = __float2bfloat16_rn(v.y);
    out[i4 + 2] = __float2bfloat16_rn(v.z);
    out[i4 + 3] = __float2bfloat16_rn(v.w);
}

// single weight transpose: W [K][N] fp32 -> Wt [N][K] bf16 (W_g1: K=512,N=256)
__global__ void k_convT1(const float* __restrict__ W, __nv_bfloat16* __restrict__ Wt) {
    __shared__ float tile[32][33];
    int lb = blockIdx.x;                      // 128 blocks
    int n0 = (lb % (HH / 32)) * 32, k0 = (lb / (HH / 32)) * 32;
    tile[threadIdx.y][threadIdx.x] = W[(size_t)(k0 + threadIdx.y) * HH + n0 + threadIdx.x];
    __syncthreads();
    Wt[(size_t)(n0 + threadIdx.y) * DD + k0 + threadIdx.x] =
        __float2bfloat16_rn(tile[threadIdx.x][threadIdx.y]);
}

// 3 weight transposes in one launch (W_g2, W_img1, W_img2)
__global__ void k_convT3(const float* __restrict__ w2, __nv_bfloat16* __restrict__ o2,
                         const float* __restrict__ w3, __nv_bfloat16* __restrict__ o3,
                         const float* __restrict__ w4, __nv_bfloat16* __restrict__ o4) {
    __shared__ float tile[32][33];
    int b = blockIdx.x;
    const float* W;
    __nv_bfloat16* Wt;
    int K, N, lb;
    if (b < 128)      { W = w2; Wt = o2; K = HH; N = DD; lb = b; }
    else if (b < 256) { W = w3; Wt = o3; K = DD; N = HH; lb = b - 128; }
    else              { W = w4; Wt = o4; K = HH; N = DD; lb = b - 256; }
    int nx = N / 32;
    int n0 = (lb % nx) * 32, k0 = (lb / nx) * 32;
    tile[threadIdx.y][threadIdx.x] = W[(size_t)(k0 + threadIdx.y) * N + n0 + threadIdx.x];
    __syncthreads();
    Wt[(size_t)(n0 + threadIdx.y) * K + k0 + threadIdx.x] =
        __float2bfloat16_rn(tile[threadIdx.x][threadIdx.y]);
}

// ------- GCN aggregation: warp-per-edge, uint4 gathers, smem reduce --------
template <bool RELU, bool BIAS>
__global__ void k_aggw(const __nv_bfloat16* __restrict__ xw, const float* __restrict__ bias,
                       __nv_bfloat16* __restrict__ out, const int* __restrict__ IDX) {
    __shared__ float red[8][256];
    int v = IDX ? IDX[blockIdx.x] : blockIdx.x;
    int warp = threadIdx.x >> 5, lane = threadIdx.x & 31;
    int rs = g_offsets[v], cnt = g_counts[v];
    float acc[8] = {0.f, 0.f, 0.f, 0.f, 0.f, 0.f, 0.f, 0.f};
    for (int i = warp; i < cnt; i += 8) {
        int s = g_srcs[rs + i];
        float w = g_wts[rs + i];
        uint4 d = *(const uint4*)(xw + (size_t)s * 256 + lane * 8);
        const __nv_bfloat162* p = (const __nv_bfloat162*)&d;
#pragma unroll
        for (int j = 0; j < 4; j++) {
            float2 f = __bfloat1622float2(p[j]);
            acc[2 * j]     += w * f.x;
            acc[2 * j + 1] += w * f.y;
        }
    }
#pragma unroll
    for (int j = 0; j < 8; j++) red[warp][lane * 8 + j] = acc[j];
    __syncthreads();
    int f = threadIdx.x;
    float dv = g_dinv[v];
    float a = dv * dv * __bfloat162float(xw[(size_t)v * 256 + f]);
#pragma unroll
    for (int w2 = 0; w2 < 8; w2++) a += red[w2][f];
    if (BIAS) a += bias[f];
    out[(size_t)blockIdx.x * 256 + f] = __float2bfloat16_rn(RELU ? fmaxf(a, 0.f) : a);
}

// ---------------- cp.async / ldmatrix helpers ----------------
__device__ __forceinline__ void cp16(uint32_t smem, const void* gmem, int srcBytes) {
    asm volatile("cp.async.cg.shared.global [%0], [%1], 16, %2;"
                 :: "r"(smem), "l"(gmem), "r"(srcBytes));
}
__device__ __forceinline__ void cp_commit() { asm volatile("cp.async.commit_group;"); }
template <int N>
__device__ __forceinline__ void cp_wait() { asm volatile("cp.async.wait_group %0;" :: "n"(N)); }

__device__ __forceinline__ void ldsm4(uint32_t& r0, uint32_t& r1, uint32_t& r2, uint32_t& r3,
                                      uint32_t addr) {
    asm volatile("ldmatrix.sync.aligned.m8n8.x4.shared.b16 {%0,%1,%2,%3}, [%4];"
                 : "=r"(r0), "=r"(r1), "=r"(r2), "=r"(r3) : "r"(addr));
}

__device__ __forceinline__ uint32_t smem_u32(const void* p) {
    uint32_t a;
    asm("{ .reg .u64 t; cvta.to.shared.u64 t, %1; cvt.u32.u64 %0, t; }" : "=r"(a) : "l"(p));
    return a;
}

#define SSTR 40  // smem row stride in bf16 elems (80B, ldmatrix-aligned, conflict-free)
#define STGB (128 * SSTR * 2)

#define MMA(acc, a0, a1, a2, a3, b0, b1)                                     \
    asm volatile(                                                            \
        "mma.sync.aligned.m16n8k16.row.col.f32.bf16.bf16.f32 "               \
        "{%0,%1,%2,%3}, {%4,%5,%6,%7}, {%8,%9}, {%0,%1,%2,%3};"              \
        : "+f"((acc)[0]), "+f"((acc)[1]), "+f"((acc)[2]), "+f"((acc)[3])     \
        : "r"(a0), "r"(a1), "r"(a2), "r"(a3), "r"(b0), "r"(b1))

// 64x32 warp tile from one 128x32 As/Bs stage
__device__ __forceinline__ void mma_tile(uint32_t sAs, uint32_t sBs,
                                         int wm, int wn, int lane,
                                         float acc[4][4][4]) {
    const int aRow = (lane & 7) + ((lane >> 3) & 1) * 8;
    const int aCol = (lane >> 4) * 8;
    const int bRow = (lane & 7) + (lane >> 4) * 8;
    const int bCol = ((lane >> 3) & 1) * 8;
#pragma unroll
    for (int kk = 0; kk < 32; kk += 16) {
        uint32_t af[4][4], bf[4][2];
#pragma unroll
        for (int mi = 0; mi < 4; mi++) {
            uint32_t a = sAs + ((wm + mi * 16 + aRow) * SSTR + kk + aCol) * 2;
            ldsm4(af[mi][0], af[mi][1], af[mi][2], af[mi][3], a);
        }
#pragma unroll
        for (int p = 0; p < 2; p++) {
            uint32_t b = sBs + ((wn + p * 16 + bRow) * SSTR + kk + bCol) * 2;
            ldsm4(bf[2 * p][0], bf[2 * p][1], bf[2 * p + 1][0], bf[2 * p + 1][1], b);
        }
#pragma unroll
        for (int mi = 0; mi < 4; mi++)
#pragma unroll
            for (int ni = 0; ni < 4; ni++)
                MMA(acc[mi][ni], af[mi][0], af[mi][1], af[mi][2], af[mi][3],
                    bf[ni][0], bf[ni][1]);
    }
}

#define GEMM_MAINLOOP(nK, ISSUE)                                             \
    ISSUE(0, 0); cp_commit();                                                \
    ISSUE(32, 1); cp_commit();                                               \
    for (int i = 0; i < (nK); i++) {                                         \
        cp_wait<1>();                                                        \
        __syncthreads();                                                     \
        if (i + 2 < (nK)) { ISSUE((i + 2) * 32, (i + 2) % 3); }              \
        cp_commit();                                                         \
        mma_tile(sAbase + ((i % 3) * STGB), sBbase + ((i % 3) * STGB),       \
                 wm, wn, lane, acc);                                         \
    }

// ---------------- bf16 NT GEMM (mma.sync), 3-stage cp.async ---------------
template <bool RELU, bool BIAS>
__global__ void bgemm(int M, int N, int K,
                      const __nv_bfloat16* __restrict__ A,
                      const __nv_bfloat16* __restrict__ B,
                      __nv_bfloat16* __restrict__ C,
                      const float* __restrict__ bias) {
    __shared__ __align__(16) __nv_bfloat16 As[3][128 * SSTR];
    __shared__ __align__(16) __nv_bfloat16 Bs[3][128 * SSTR];
    const int tid = threadIdx.x;
    const int lane = tid & 31, warp = tid >> 5;
    const int wm = (warp & 1) * 64, wn = (warp >> 1) * 32;
    const int g = lane >> 2, tg = lane & 3;
    const int brow = blockIdx.y * 128, bcol = blockIdx.x * 128;

    float acc[4][4][4];
#pragma unroll
    for (int a = 0; a < 4; a++)
#pragma unroll
        for (int b = 0; b < 4; b++)
#pragma unroll
            for (int c = 0; c < 4; c++) acc[a][b][c] = 0.f;

    const int lrow = tid >> 1;
    const int lk = (tid & 1) * 16;
    int arow = brow + lrow;
    bool aval = arow < M;
    int aSrc = aval ? 16 : 0;
    const __nv_bfloat16* Ap = A + (long)(aval ? arow : 0) * K + lk;
    const __nv_bfloat16* Bp = B + (long)(bcol + lrow) * K + lk;

    uint32_t sAbase = smem_u32(&As[0][0]);
    uint32_t sBbase = smem_u32(&Bs[0][0]);
    uint32_t sA = sAbase + (lrow * SSTR + lk) * 2;
    uint32_t sB = sBbase + (lrow * SSTR + lk) * 2;

    const int nK = K / 32;
#define ISSUE_G(k0, slot)                                                    \
    cp16(sA + (slot) * STGB, Ap + (k0), aSrc);                               \
    cp16(sA + (slot) * STGB + 16, Ap + (k0) + 8, aSrc);                      \
    cp16(sB + (slot) * STGB, Bp + (k0), 16);                                 \
    cp16(sB + (slot) * STGB + 16, Bp + (k0) + 8, 16);
    GEMM_MAINLOOP(nK, ISSUE_G)
#undef ISSUE_G

#pragma unroll
    for (int mi = 0; mi < 4; mi++) {
#pragma unroll
        for (int half = 0; half < 2; half++) {
            int r = brow + wm + mi * 16 + g + half * 8;
            if (r >= M) continue;
#pragma unroll
            for (int ni = 0; ni < 4; ni++) {
                int c = bcol + wn + ni * 8 + tg * 2;
                float v0 = acc[mi][ni][half * 2 + 0];
                float v1 = acc[mi][ni][half * 2 + 1];
                if (BIAS) { v0 += bias[c]; v1 += bias[c + 1]; }
                if (RELU) { v0 = fmaxf(v0, 0.f); v1 = fmaxf(v1, 0.f); }
                __nv_bfloat162 h;
                h.x = __float2bfloat16_rn(v0);
                h.y = __float2bfloat16_rn(v1);
                *(__nv_bfloat162*)(C + (size_t)r * N + c) = h;
            }
        }
    }
}

// ------ L1 GEMM with fused fp32->bf16 A conversion (N=256, K=512) ----------
// A fp32 via register-staged LDG (1 stage ahead) + STS bf16; B via cp.async.
// 2-slot smem ring, cp issued exactly 1 stage ahead.  (R13 proven config)
__global__ void bgemm_convA(int M, const float* __restrict__ Af,
                            const __nv_bfloat16* __restrict__ B,
                            __nv_bfloat16* __restrict__ C) {
    __shared__ __align__(16) __nv_bfloat16 As[2][128 * SSTR];
    __shared__ __align__(16) __nv_bfloat16 Bs[2][128 * SSTR];
    const int tid = threadIdx.x;
    const int lane = tid & 31, warp = tid >> 5;
    const int wm = (warp & 1) * 64, wn = (warp >> 1) * 32;
    const int g = lane >> 2, tg = lane & 3;
    const int brow = blockIdx.y * 128, bcol = blockIdx.x * 128;

    float acc[4][4][4];
#pragma unroll
    for (int a = 0; a < 4; a++)
#pragma unroll
        for (int b = 0; b < 4; b++)
#pragma unroll
            for (int c = 0; c < 4; c++) acc[a][b][c] = 0.f;

    const int lrow = tid >> 1;
    const int lk = (tid & 1) * 16;
    int arow = brow + lrow;
    bool aval = arow < M;
    const float* Ap = Af + (long)(aval ? arow : 0) * DD + lk;
    const __nv_bfloat16* Bp = B + (long)(bcol + lrow) * DD + lk;

    uint32_t sAbase = smem_u32(&As[0][0]);
    uint32_t sBbase = smem_u32(&Bs[0][0]);
    uint32_t sB = sBbase + (lrow * SSTR + lk) * 2;

    float4 a4[4];
#define LDA(k0)                                                              \
    if (aval) {                                                              \
        a4[0] = *(const float4*)(Ap + (k0));                                 \
        a4[1] = *(const float4*)(Ap + (k0) + 4);                             \
        a4[2] = *(const float4*)(Ap + (k0) + 8);                             \
        a4[3] = *(const float4*)(Ap + (k0) + 12);                            \
    } else {                                                                 \
        a4[0] = a4[1] = a4[2] = a4[3] = make_float4(0.f, 0.f, 0.f, 0.f);     \
    }
#define STA(slot)                                                            \
    {                                                                        \
        uint4 u0, u1;                                                        \
        __nv_bfloat162* q0 = (__nv_bfloat162*)&u0;                           \
        __nv_bfloat162* q1 = (__nv_bfloat162*)&u1;                           \
        q0[0] = __float22bfloat162_rn(make_float2(a4[0].x, a4[0].y));        \
        q0[1] = __float22bfloat162_rn(make_float2(a4[0].z, a4[0].w));        \
        q0[2] = __float22bfloat162_rn(make_float2(a4[1].x, a4[1].y));        \
        q0[3] = __float22bfloat162_rn(make_float2(a4[1].z, a4[1].w));        \
        q1[0] = __float22bfloat162_rn(make_float2(a4[2].x, a4[2].y));        \
        q1[1] = __float22bfloat162_rn(make_float2(a4[2].z, a4[2].w));        \
        q1[2] = __float22bfloat162_rn(make_float2(a4[3].x, a4[3].y));        \
        q1[3] = __float22bfloat162_rn(make_float2(a4[3].z, a4[3].w));        \
        *(uint4*)&As[slot][lrow * SSTR + lk] = u0;                           \
        *(uint4*)&As[slot][lrow * SSTR + lk + 8] = u1;                       \
    }

    const int nK = DD / 32;  // 16
    LDA(0);
    STA(0);
    LDA(32);
    cp16(sB, Bp, 16); cp16(sB + 16, Bp + 8, 16);
    cp_commit();

    for (int i = 0; i < nK; i++) {
        cp_wait<0>();
        __syncthreads();
        if (i + 1 < nK) {
            STA((i + 1) & 1);
            if (i + 2 < nK) { LDA((i + 2) * 32); }
            int slot = (i + 1) & 1;
            cp16(sB + slot * STGB, Bp + (i + 1) * 32, 16);
            cp16(sB + slot * STGB + 16, Bp + (i + 1) * 32 + 8, 16);
            cp_commit();
        } else {
            cp_commit();
        }
        mma_tile(sAbase + (i & 1) * STGB, sBbase + (i & 1) * STGB,
                 wm, wn, lane, acc);
    }
#undef LDA
#undef STA

#pragma unroll
    for (int mi = 0; mi < 4; mi++) {
#pragma unroll
        for (int half = 0; half < 2; half++) {
            int r = brow + wm + mi * 16 + g + half * 8;
            if (r >= M) continue;
#pragma unroll
            for (int ni = 0; ni < 4; ni++) {
                int c = bcol + wn + ni * 8 + tg * 2;
                __nv_bfloat162 h;
                h.x = __float2bfloat16_rn(acc[mi][ni][half * 2 + 0]);
                h.y = __float2bfloat16_rn(acc[mi][ni][half * 2 + 1]);
                *(__nv_bfloat162*)(C + (size_t)r * HH + c) = h;
            }
        }
    }
}

// ------- fused logits GEMM + online row LSE + diag --------------------------
// grid = (NCHUNK=16, NB/128=32) = 512 CTAs; each block: 128 rows x 256 cols
// (2 tiles of 128), R11-style per-tile pipeline.
__global__ void k_logits_lse(const __nv_bfloat16* __restrict__ A,   // gcn_lbl [NB][DD]
                             const __nv_bfloat16* __restrict__ B) { // img [NB][DD]
    __shared__ __align__(16) __nv_bfloat16 As[3][128 * SSTR];
    __shared__ __align__(16) __nv_bfloat16 Bs[3][128 * SSTR];
    __shared__ float red_m[4][128];
    __shared__ float red_s[4][128];

    const int tid = threadIdx.x;
    const int lane = tid & 31, warp = tid >> 5;
    const int wm = (warp & 1) * 64, wn = (warp >> 1) * 32;
    const int wnIdx = warp >> 1;
    const int g = lane >> 2, tg = lane & 3;
    const int brow = blockIdx.y * 128;
    const int chunk = blockIdx.x;

    const int lrow = tid >> 1;
    const int lk = (tid & 1) * 16;
    const __nv_bfloat16* Ap = A + (long)(brow + lrow) * DD + lk;

    uint32_t sAbase = smem_u32(&As[0][0]);
    uint32_t sBbase = smem_u32(&Bs[0][0]);
    uint32_t sA = sAbase + (lrow * SSTR + lk) * 2;
    uint32_t sB = sBbase + (lrow * SSTR + lk) * 2;

    float run_m = -3.0e38f, run_s = 0.f;  // valid for tid < 128 (row = tid)

    for (int nt = 0; nt < 2; nt++) {
        const int bcol = chunk * 256 + nt * 128;
        const __nv_bfloat16* Bp = B + (long)(bcol + lrow) * DD + lk;

        float acc[4][4][4];
#pragma unroll
        for (int a = 0; a < 4; a++)
#pragma unroll
            for (int b = 0; b < 4; b++)
#pragma unroll
                for (int c = 0; c < 4; c++) acc[a][b][c] = 0.f;

        const int nK = DD / 32;  // 16
#define ISSUE_L(k0, slot)                                                    \
    cp16(sA + (slot) * STGB, Ap + (k0), 16);                                 \
    cp16(sA + (slot) * STGB + 16, Ap + (k0) + 8, 16);                        \
    cp16(sB + (slot) * STGB, Bp + (k0), 16);                                 \
    cp16(sB + (slot) * STGB + 16, Bp + (k0) + 8, 16);
        GEMM_MAINLOOP(nK, ISSUE_L)
#undef ISSUE_L
        __syncthreads();  // mainloop reads done; also fences red_* reuse

        // ---- per warp-column local (max, sumexp) + diag, one smem round ----
#pragma unroll
        for (int mi = 0; mi < 4; mi++) {
#pragma unroll
            for (int half = 0; half < 2; half++) {
                int row = wm + mi * 16 + g + half * 8;
                float v = -3.0e38f;
#pragma unroll
                for (int ni = 0; ni < 4; ni++)
                    v = fmaxf(v, fmaxf(acc[mi][ni][half * 2], acc[mi][ni][half * 2 + 1]));
                v = fmaxf(v, __shfl_xor_sync(0xffffffffu, v, 1));
                v = fmaxf(v, __shfl_xor_sync(0xffffffffu, v, 2));
                float ps = 0.f;
#pragma unroll
                for (int ni = 0; ni < 4; ni++) {
#pragma unroll
                    for (int j = 0; j < 2; j++) {
                        float x = acc[mi][ni][half * 2 + j];
                        ps += __expf(x - v);
                        int gc = bcol + wn + ni * 8 + tg * 2 + j;
                        if (gc == brow + row) g_diag[gc] = x;
                    }
                }
                ps += __shfl_xor_sync(0xffffffffu, ps, 1);
                ps += __shfl_xor_sync(0xffffffffu, ps, 2);
                if (tg == 0) { red_m[wnIdx][row] = v; red_s[wnIdx][row] = ps; }
            }
        }
        __syncthreads();
        if (tid < 128) {
            float m0 = red_m[0][tid], m1 = red_m[1][tid];
            float m2 = red_m[2][tid], m3 = red_m[3][tid];
            float M = fmaxf(fmaxf(m0, m1), fmaxf(m2, m3));
            float S = red_s[0][tid] * __expf(m0 - M) + red_s[1][tid] * __expf(m1 - M)
                    + red_s[2][tid] * __expf(m2 - M) + red_s[3][tid] * __expf(m3 - M);
            float nm = fmaxf(run_m, M);
            run_s = run_s * __expf(run_m - nm) + S * __expf(M - nm);
            run_m = nm;
        }
        // no extra sync: next tile's mainloop syncs before red_* is rewritten
    }

    if (tid < 128) {
        g_pm[chunk * NB + brow + tid] = run_m;
        g_ps[chunk * NB + brow + tid] = run_s;
    }
}

// ---------- merge partials: stage 1 (32 blocks x 128 rows) ----------
__global__ void k_merge(const int* __restrict__ label) {
    __shared__ float sh[128];
    int i = blockIdx.x * 128 + threadIdx.x;
    float m = -3.0e38f;
#pragma unroll
    for (int c = 0; c < NCHUNK; c++) m = fmaxf(m, g_pm[c * NB + i]);
    float s = 0.f;
#pragma unroll
    for (int c = 0; c < NCHUNK; c++) s += g_ps[c * NB + i] * __expf(g_pm[c * NB + i] - m);
    float lse = m + logf(s);
    sh[threadIdx.x] = -(float)label[i] * (g_diag[i] - lse);
    __syncthreads();
    for (int off = 64; off > 0; off >>= 1) {
        if (threadIdx.x < off) sh[threadIdx.x] += sh[threadIdx.x + off];
        __syncthreads();
    }
    if (threadIdx.x == 0) g_part[blockIdx.x] = sh[0];
}

// ---------- stage 2: final scalar ----------
__global__ void k_final(float* __restrict__ out) {
    float v = g_part[threadIdx.x];  // 32 threads
#pragma unroll
    for (int off = 16; off > 0; off >>= 1)
        v += __shfl_xor_sync(0xffffffffu, v, off);
    if (threadIdx.x == 0) out[0] = v / (float)NB + 1.0f;  // + triplet (==1 exactly)
}

// ---------------- launch ----------------
extern "C" void kernel_launch(void* const* d_in, const int* in_sizes, int n_in,
                              void* d_out, int out_size) {
    const float* image  = (const float*)d_in[0];
    const float* xnodes = (const float*)d_in[1];
    const int*   ei     = (const int*)d_in[2];
    const int*   label  = (const int*)d_in[3];
    const float* W_img1 = (const float*)d_in[4];
    const float* b_img1 = (const float*)d_in[5];
    const float* W_img2 = (const float*)d_in[6];
    const float* b_img2 = (const float*)d_in[7];
    const float* W_g1   = (const float*)d_in[8];
    const float* b_g1   = (const float*)d_in[9];
    const float* W_g2   = (const float*)d_in[10];
    const float* b_g2   = (const float*)d_in[11];

    __nv_bfloat16 *p_ia, *p_wg1t, *p_wg2t, *p_wi1t, *p_wi2t;
    __nv_bfloat16 *p_xw1, *p_h, *p_aggl, *p_gcn, *p_t1, *p_img;
    int *p_counts, *p_cursor;
    cudaGetSymbolAddress((void**)&p_ia, g_ia);
    cudaGetSymbolAddress((void**)&p_wg1t, g_wg1t);
    cudaGetSymbolAddress((void**)&p_wg2t, g_wg2t);
    cudaGetSymbolAddress((void**)&p_wi1t, g_wi1t);
    cudaGetSymbolAddress((void**)&p_wi2t, g_wi2t);
    cudaGetSymbolAddress((void**)&p_xw1, g_xw1);
    cudaGetSymbolAddress((void**)&p_h, g_h);
    cudaGetSymbolAddress((void**)&p_aggl, g_aggl);
    cudaGetSymbolAddress((void**)&p_gcn, g_gcn);
    cudaGetSymbolAddress((void**)&p_t1, g_t1);
    cudaGetSymbolAddress((void**)&p_img, g_img);
    cudaGetSymbolAddress((void**)&p_counts, g_counts);
    cudaGetSymbolAddress((void**)&p_cursor, g_cursor);

    // one-time stream/event setup
    static cudaStream_t sCsr = nullptr, sMlp = nullptr;
    static cudaEvent_t evRoot, evCsr, evT3, evMlp;
    if (sCsr == nullptr) {
        cudaStreamCreateWithFlags(&sCsr, cudaStreamNonBlocking);
        cudaStreamCreateWithFlags(&sMlp, cudaStreamNonBlocking);
        cudaEventCreateWithFlags(&evRoot, cudaEventDisableTiming);
        cudaEventCreateWithFlags(&evCsr, cudaEventDisableTiming);
        cudaEventCreateWithFlags(&evT3, cudaEventDisableTiming);
        cudaEventCreateWithFlags(&evMlp, cudaEventDisableTiming);
    }

    // fork point
    cudaEventRecord(evRoot, 0);

    // ---- branch 1 (sCsr): CSR build ----
    cudaStreamWaitEvent(sCsr, evRoot, 0);
    cudaMemsetAsync(p_counts, 0, NN * sizeof(int), sCsr);
    cudaMemsetAsync(p_cursor, 0, NN * sizeof(int), sCsr);
    k_count<<<(NE + 255) / 256, 256, 0, sCsr>>>(ei);
    k_scan<<<1, 1024, 0, sCsr>>>();
    k_fill<<<(NE + 255) / 256, 256, 0, sCsr>>>(ei);
    cudaEventRecord(evCsr, sCsr);

    // ---- branch 2 (sMlp): other transposes + image convert + MLP ----
    cudaStreamWaitEvent(sMlp, evRoot, 0);
    k_convT3<<<384, dim3(32, 32), 0, sMlp>>>(W_g2, p_wg2t, W_img1, p_wi1t, W_img2, p_wi2t);
    cudaEventRecord(evT3, sMlp);
    k_conv<<<(NB * DD / 4 + 255) / 256, 256, 0, sMlp>>>(image, p_ia, NB * DD);
    {
        dim3 grid(HH / 128, NB / 128);
        bgemm<true, true><<<grid, 256, 0, sMlp>>>(NB, HH, DD, p_ia, p_wi1t, p_t1, b_img1);
    }
    {
        dim3 grid(DD / 128, NB / 128);
        bgemm<true, true><<<grid, 256, 0, sMlp>>>(NB, DD, HH, p_t1, p_wi2t, p_img, b_img2);
    }
    cudaEventRecord(evMlp, sMlp);

    // ---- main stream: W_g1 transpose only, then GCN chain ----
    k_convT1<<<128, dim3(32, 32)>>>(W_g1, p_wg1t);
    {
        dim3 grid(HH / 128, (NN + 127) / 128);
        bgemm_convA<<<grid, 256>>>(NN, xnodes, p_wg1t, p_xw1);
    }
    cudaStreamWaitEvent(0, evCsr, 0);
    k_aggw<true, true><<<NN, 256>>>(p_xw1, b_g1, p_h, nullptr);
    k_aggw<false, false><<<NB, 256>>>(p_h, nullptr, p_aggl, label);
    cudaStreamWaitEvent(0, evT3, 0);
    {
        dim3 grid(DD / 128, NB / 128);
        bgemm<false, true><<<grid, 256>>>(NB, DD, HH, p_aggl, p_wg2t, p_gcn, b_g2);
    }

    // ---- join MLP, then fused logits + LSE ----
    cudaStreamWaitEvent(0, evMlp, 0);
    {
        dim3 grid(NCHUNK, NB / 128);
        k_logits_lse<<<grid, 256>>>(p_gcn, p_img);
    }
    k_merge<<<32, 128>>>(label);
    k_final<<<1, 32>>>((float*)d_out);
}

// round 16
// speedup vs baseline: 1.1889x; 1.1753x over previous
#include <cuda_runtime.h>
#include <cuda_bf16.h>
#include <cstdint>

#define NN 10000   // nodes
#define NE 160000  // edges
#define NB 4096    // batch
#define DD 512
#define HH 256
#define NCHUNK 16  // column chunks (256 cols each) for fused logits+lse

// ---------------- scratch (device globals; no runtime alloc) ----------------
__device__ __nv_bfloat16 g_ia[NB * DD];
__device__ __nv_bfloat16 g_wg1t[HH * DD];
__device__ __nv_bfloat16 g_wg2b[HH * DD];    // W_g2 bf16 (native [256][512], NT-ready)
__device__ __nv_bfloat16 g_wi1t[HH * DD];
__device__ __nv_bfloat16 g_wi2t[DD * HH];
__device__ __nv_bfloat16 g_xw1[NN * HH];     // layer-1 xw
__device__ __nv_bfloat16 g_h[NN * HH];       // layer-1 output (all nodes)
__device__ __nv_bfloat16 g_aggl[NB * HH];    // agg(h) at label rows
__device__ __nv_bfloat16 g_m2[NB * HH];      // M2 = img @ W_g2^T  [NB][256]
__device__ __nv_bfloat16 g_t1[NB * HH];
__device__ __nv_bfloat16 g_img[NB * DD];
__device__ float g_cvec[NB];                 // c[j] = dot(b_g2, img[j])
__device__ float g_pm[NCHUNK * NB];
__device__ float g_ps[NCHUNK * NB];
__device__ float g_diag[NB];
__device__ float g_part[32];
__device__ float g_dinv[NN];
__device__ int   g_counts[NN];
__device__ int   g_offsets[NN];
__device__ int   g_cursor[NN];
__device__ int   g_srcs[NE];
__device__ float g_wts[NE];

// ---------------- graph preprocessing ----------------
__global__ void k_count(const int* __restrict__ ei) {
    int e = blockIdx.x * blockDim.x + threadIdx.x;
    if (e < NE) atomicAdd(&g_counts[ei[NE + e]], 1);
}

__global__ void k_scan() {
    __shared__ int wsum[32];
    const int CH = 10;
    int t = threadIdx.x;
    int lane = t & 31, warp = t >> 5;
    int base = t * CH;
    int loc[CH];
    int sum = 0;
#pragma unroll
    for (int j = 0; j < CH; j++) {
        int idx = base + j;
        int c = (idx < NN) ? g_counts[idx] : 0;
        loc[j] = c; sum += c;
        if (idx < NN) g_dinv[idx] = rsqrtf(1.0f + (float)c);
    }
    int inc = sum;
#pragma unroll
    for (int off = 1; off < 32; off <<= 1) {
        int v = __shfl_up_sync(0xffffffffu, inc, off);
        if (lane >= off) inc += v;
    }
    if (lane == 31) wsum[warp] = inc;
    __syncthreads();
    if (warp == 0) {
        int v = wsum[lane];
        int wi = v;
#pragma unroll
        for (int off = 1; off < 32; off <<= 1) {
            int u = __shfl_up_sync(0xffffffffu, wi, off);
            if (lane >= off) wi += u;
        }
        wsum[lane] = wi - v;
    }
    __syncthreads();
    int run = wsum[warp] + (inc - sum);
#pragma unroll
    for (int j = 0; j < CH; j++) {
        int idx = base + j;
        if (idx < NN) g_offsets[idx] = run;
        run += loc[j];
    }
}

__global__ void k_fill(const int* __restrict__ ei) {
    int e = blockIdx.x * blockDim.x + threadIdx.x;
    if (e < NE) {
        int s = ei[e], d = ei[NE + e];
        int pos = g_offsets[d] + atomicAdd(&g_cursor[d], 1);
        g_srcs[pos] = s;
        g_wts[pos] = g_dinv[s] * g_dinv[d];
    }
}

// ---------------- fp32 -> bf16 convert ----------------
__global__ void k_conv(const float* __restrict__ in, __nv_bfloat16* __restrict__ out, int n) {
    int i4 = (blockIdx.x * blockDim.x + threadIdx.x) * 4;
    if (i4 >= n) return;
    float4 v = *(const float4*)(in + i4);
    out[i4 + 0] = __float2bfloat16_rn(v.x);
    out[i4 + 1] = __float2bfloat16_rn(v.y);
    out[i4 + 2] = __float2bfloat16_rn(v.z);
    out[i4 + 3] = __float2bfloat16_rn(v.w);
}

// single weight transpose: W [K][N] fp32 -> Wt [N][K] bf16 (W_g1: K=512,N=256)
__global__ void k_convT1(const float* __restrict__ W, __nv_bfloat16* __restrict__ Wt) {
    __shared__ float tile[32][33];
    int lb = blockIdx.x;                      // 128 blocks
    int n0 = (lb % (HH / 32)) * 32, k0 = (lb / (HH / 32)) * 32;
    tile[threadIdx.y][threadIdx.x] = W[(size_t)(k0 + threadIdx.y) * HH + n0 + threadIdx.x];
    __syncthreads();
    Wt[(size_t)(n0 + threadIdx.y) * DD + k0 + threadIdx.x] =
        __float2bfloat16_rn(tile[threadIdx.x][threadIdx.y]);
}

// 2 weight transposes in one launch (W_img1, W_img2)
__global__ void k_convT2(const float* __restrict__ w3, __nv_bfloat16* __restrict__ o3,
                         const float* __restrict__ w4, __nv_bfloat16* __restrict__ o4) {
    __shared__ float tile[32][33];
    int b = blockIdx.x;
    const float* W;
    __nv_bfloat16* Wt;
    int K, N, lb;
    if (b < 128) { W = w3; Wt = o3; K = DD; N = HH; lb = b; }
    else         { W = w4; Wt = o4; K = HH; N = DD; lb = b - 128; }
    int nx = N / 32;
    int n0 = (lb % nx) * 32, k0 = (lb / nx) * 32;
    tile[threadIdx.y][threadIdx.x] = W[(size_t)(k0 + threadIdx.y) * N + n0 + threadIdx.x];
    __syncthreads();
    Wt[(size_t)(n0 + threadIdx.y) * K + k0 + threadIdx.x] =
        __float2bfloat16_rn(tile[threadIdx.x][threadIdx.y]);
}

// cvec[j] = dot(b_g2, img[j,:])  (warp per row; deterministic order)
__global__ void k_cvec(const __nv_bfloat16* __restrict__ img,
                       const float* __restrict__ b2, float* __restrict__ cv) {
    int row = blockIdx.x * 8 + (threadIdx.x >> 5);
    int lane = threadIdx.x & 31;
    const __nv_bfloat16* p = img + (size_t)row * DD + lane * 16;
    float s = 0.f;
#pragma unroll
    for (int t = 0; t < 2; t++) {
        uint4 d = *(const uint4*)(p + t * 8);
        const __nv_bfloat162* q = (const __nv_bfloat162*)&d;
#pragma unroll
        for (int j = 0; j < 4; j++) {
            float2 f = __bfloat1622float2(q[j]);
            int c0 = lane * 16 + t * 8 + 2 * j;
            s += f.x * b2[c0] + f.y * b2[c0 + 1];
        }
    }
#pragma unroll
    for (int off = 16; off > 0; off >>= 1)
        s += __shfl_xor_sync(0xffffffffu, s, off);
    if (lane == 0) cv[row] = s;
}

// ------- GCN aggregation: warp-per-edge, uint4 gathers, smem reduce --------
template <bool RELU, bool BIAS>
__global__ void k_aggw(const __nv_bfloat16* __restrict__ xw, const float* __restrict__ bias,
                       __nv_bfloat16* __restrict__ out, const int* __restrict__ IDX) {
    __shared__ float red[8][256];
    int v = IDX ? IDX[blockIdx.x] : blockIdx.x;
    int warp = threadIdx.x >> 5, lane = threadIdx.x & 31;
    int rs = g_offsets[v], cnt = g_counts[v];
    float acc[8] = {0.f, 0.f, 0.f, 0.f, 0.f, 0.f, 0.f, 0.f};
    for (int i = warp; i < cnt; i += 8) {
        int s = g_srcs[rs + i];
        float w = g_wts[rs + i];
        uint4 d = *(const uint4*)(xw + (size_t)s * 256 + lane * 8);
        const __nv_bfloat162* p = (const __nv_bfloat162*)&d;
#pragma unroll
        for (int j = 0; j < 4; j++) {
            float2 f = __bfloat1622float2(p[j]);
            acc[2 * j]     += w * f.x;
            acc[2 * j + 1] += w * f.y;
        }
    }
#pragma unroll
    for (int j = 0; j < 8; j++) red[warp][lane * 8 + j] = acc[j];
    __syncthreads();
    int f = threadIdx.x;
    float dv = g_dinv[v];
    float a = dv * dv * __bfloat162float(xw[(size_t)v * 256 + f]);
#pragma unroll
    for (int w2 = 0; w2 < 8; w2++) a += red[w2][f];
    if (BIAS) a += bias[f];
    out[(size_t)blockIdx.x * 256 + f] = __float2bfloat16_rn(RELU ? fmaxf(a, 0.f) : a);
}

// ---------------- cp.async / ldmatrix helpers ----------------
__device__ __forceinline__ void cp16(uint32_t smem, const void* gmem, int srcBytes) {
    asm volatile("cp.async.cg.shared.global [%0], [%1], 16, %2;"
                 :: "r"(smem), "l"(gmem), "r"(srcBytes));
}
__device__ __forceinline__ void cp_commit() { asm volatile("cp.async.commit_group;"); }
template <int N>
__device__ __forceinline__ void cp_wait() { asm volatile("cp.async.wait_group %0;" :: "n"(N)); }

__device__ __forceinline__ void ldsm4(uint32_t& r0, uint32_t& r1, uint32_t& r2, uint32_t& r3,
                                      uint32_t addr) {
    asm volatile("ldmatrix.sync.aligned.m8n8.x4.shared.b16 {%0,%1,%2,%3}, [%4];"
                 : "=r"(r0), "=r"(r1), "=r"(r2), "=r"(r3) : "r"(addr));
}

__device__ __forceinline__ uint32_t smem_u32(const void* p) {
    uint32_t a;
    asm("{ .reg .u64 t; cvta.to.shared.u64 t, %1; cvt.u32.u64 %0, t; }" : "=r"(a) : "l"(p));
    return a;
}

#define SSTR 40  // smem row stride in bf16 elems (80B, ldmatrix-aligned, conflict-free)
#define STGB (128 * SSTR * 2)

#define MMA(acc, a0, a1, a2, a3, b0, b1)                                     \
    asm volatile(                                                            \
        "mma.sync.aligned.m16n8k16.row.col.f32.bf16.bf16.f32 "               \
        "{%0,%1,%2,%3}, {%4,%5,%6,%7}, {%8,%9}, {%0,%1,%2,%3};"              \
        : "+f"((acc)[0]), "+f"((acc)[1]), "+f"((acc)[2]), "+f"((acc)[3])     \
        : "r"(a0), "r"(a1), "r"(a2), "r"(a3), "r"(b0), "r"(b1))

// 64x32 warp tile from one 128x32 As/Bs stage
__device__ __forceinline__ void mma_tile(uint32_t sAs, uint32_t sBs,
                                         int wm, int wn, int lane,
                                         float acc[4][4][4]) {
    const int aRow = (lane & 7) + ((lane >> 3) & 1) * 8;
    const int aCol = (lane >> 4) * 8;
    const int bRow = (lane & 7) + (lane >> 4) * 8;
    const int bCol = ((lane >> 3) & 1) * 8;
#pragma unroll
    for (int kk = 0; kk < 32; kk += 16) {
        uint32_t af[4][4], bf[4][2];
#pragma unroll
        for (int mi = 0; mi < 4; mi++) {
            uint32_t a = sAs + ((wm + mi * 16 + aRow) * SSTR + kk + aCol) * 2;
            ldsm4(af[mi][0], af[mi][1], af[mi][2], af[mi][3], a);
        }
#pragma unroll
        for (int p = 0; p < 2; p++) {
            uint32_t b = sBs + ((wn + p * 16 + bRow) * SSTR + kk + bCol) * 2;
            ldsm4(bf[2 * p][0], bf[2 * p][1], bf[2 * p + 1][0], bf[2 * p + 1][1], b);
        }
#pragma unroll
        for (int mi = 0; mi < 4; mi++)
#pragma unroll
            for (int ni = 0; ni < 4; ni++)
                MMA(acc[mi][ni], af[mi][0], af[mi][1], af[mi][2], af[mi][3],
                    bf[ni][0], bf[ni][1]);
    }
}

#define GEMM_MAINLOOP(nK, ISSUE)                                             \
    ISSUE(0, 0); cp_commit();                                                \
    ISSUE(32, 1); cp_commit();                                               \
    for (int i = 0; i < (nK); i++) {                                         \
        cp_wait<1>();                                                        \
        __syncthreads();                                                     \
        if (i + 2 < (nK)) { ISSUE((i + 2) * 32, (i + 2) % 3); }              \
        cp_commit();                                                         \
        mma_tile(sAbase + ((i % 3) * STGB), sBbase + ((i % 3) * STGB),       \
                 wm, wn, lane, acc);                                         \
    }

// ---------------- bf16 NT GEMM (mma.sync), 3-stage cp.async ---------------
template <bool RELU, bool BIAS>
__global__ void bgemm(int M, int N, int K,
                      const __nv_bfloat16* __restrict__ A,
                      const __nv_bfloat16* __restrict__ B,
                      __nv_bfloat16* __restrict__ C,
                      const float* __restrict__ bias) {
    __shared__ __align__(16) __nv_bfloat16 As[3][128 * SSTR];
    __shared__ __align__(16) __nv_bfloat16 Bs[3][128 * SSTR];
    const int tid = threadIdx.x;
    const int lane = tid & 31, warp = tid >> 5;
    const int wm = (warp & 1) * 64, wn = (warp >> 1) * 32;
    const int g = lane >> 2, tg = lane & 3;
    const int brow = blockIdx.y * 128, bcol = blockIdx.x * 128;

    float acc[4][4][4];
#pragma unroll
    for (int a = 0; a < 4; a++)
#pragma unroll
        for (int b = 0; b < 4; b++)
#pragma unroll
            for (int c = 0; c < 4; c++) acc[a][b][c] = 0.f;

    const int lrow = tid >> 1;
    const int lk = (tid & 1) * 16;
    int arow = brow + lrow;
    bool aval = arow < M;
    int aSrc = aval ? 16 : 0;
    const __nv_bfloat16* Ap = A + (long)(aval ? arow : 0) * K + lk;
    const __nv_bfloat16* Bp = B + (long)(bcol + lrow) * K + lk;

    uint32_t sAbase = smem_u32(&As[0][0]);
    uint32_t sBbase = smem_u32(&Bs[0][0]);
    uint32_t sA = sAbase + (lrow * SSTR + lk) * 2;
    uint32_t sB = sBbase + (lrow * SSTR + lk) * 2;

    const int nK = K / 32;
#define ISSUE_G(k0, slot)                                                    \
    cp16(sA + (slot) * STGB, Ap + (k0), aSrc);                               \
    cp16(sA + (slot) * STGB + 16, Ap + (k0) + 8, aSrc);                      \
    cp16(sB + (slot) * STGB, Bp + (k0), 16);                                 \
    cp16(sB + (slot) * STGB + 16, Bp + (k0) + 8, 16);
    GEMM_MAINLOOP(nK, ISSUE_G)
#undef ISSUE_G

#pragma unroll
    for (int mi = 0; mi < 4; mi++) {
#pragma unroll
        for (int half = 0; half < 2; half++) {
            int r = brow + wm + mi * 16 + g + half * 8;
            if (r >= M) continue;
#pragma unroll
            for (int ni = 0; ni < 4; ni++) {
                int c = bcol + wn + ni * 8 + tg * 2;
                float v0 = acc[mi][ni][half * 2 + 0];
                float v1 = acc[mi][ni][half * 2 + 1];
                if (BIAS) { v0 += bias[c]; v1 += bias[c + 1]; }
                if (RELU) { v0 = fmaxf(v0, 0.f); v1 = fmaxf(v1, 0.f); }
                __nv_bfloat162 h;
                h.x = __float2bfloat16_rn(v0);
                h.y = __float2bfloat16_rn(v1);
                *(__nv_bfloat162*)(C + (size_t)r * N + c) = h;
            }
        }
    }
}

// ------ L1 GEMM with fused fp32->bf16 A conversion (N=256, K=512) ----------
__global__ void bgemm_convA(int M, const float* __restrict__ Af,
                            const __nv_bfloat16* __restrict__ B,
                            __nv_bfloat16* __restrict__ C) {
    __shared__ __align__(16) __nv_bfloat16 As[2][128 * SSTR];
    __shared__ __align__(16) __nv_bfloat16 Bs[2][128 * SSTR];
    const int tid = threadIdx.x;
    const int lane = tid & 31, warp = tid >> 5;
    const int wm = (warp & 1) * 64, wn = (warp >> 1) * 32;
    const int g = lane >> 2, tg = lane & 3;
    const int brow = blockIdx.y * 128, bcol = blockIdx.x * 128;

    float acc[4][4][4];
#pragma unroll
    for (int a = 0; a < 4; a++)
#pragma unroll
        for (int b = 0; b < 4; b++)
#pragma unroll
            for (int c = 0; c < 4; c++) acc[a][b][c] = 0.f;

    const int lrow = tid >> 1;
    const int lk = (tid & 1) * 16;
    int arow = brow + lrow;
    bool aval = arow < M;
    const float* Ap = Af + (long)(aval ? arow : 0) * DD + lk;
    const __nv_bfloat16* Bp = B + (long)(bcol + lrow) * DD + lk;

    uint32_t sAbase = smem_u32(&As[0][0]);
    uint32_t sBbase = smem_u32(&Bs[0][0]);
    uint32_t sB = sBbase + (lrow * SSTR + lk) * 2;

    float4 a4[4];
#define LDA(k0)                                                              \
    if (aval) {                                                              \
        a4[0] = *(const float4*)(Ap + (k0));                                 \
        a4[1] = *(const float4*)(Ap + (k0) + 4);                             \
        a4[2] = *(const float4*)(Ap + (k0) + 8);                             \
        a4[3] = *(const float4*)(Ap + (k0) + 12);                            \
    } else {                                                                 \
        a4[0] = a4[1] = a4[2] = a4[3] = make_float4(0.f, 0.f, 0.f, 0.f);     \
    }
#define STA(slot)                                                            \
    {                                                                        \
        uint4 u0, u1;                                                        \
        __nv_bfloat162* q0 = (__nv_bfloat162*)&u0;                           \
        __nv_bfloat162* q1 = (__nv_bfloat162*)&u1;                           \
        q0[0] = __float22bfloat162_rn(make_float2(a4[0].x, a4[0].y));        \
        q0[1] = __float22bfloat162_rn(make_float2(a4[0].z, a4[0].w));        \
        q0[2] = __float22bfloat162_rn(make_float2(a4[1].x, a4[1].y));        \
        q0[3] = __float22bfloat162_rn(make_float2(a4[1].z, a4[1].w));        \
        q1[0] = __float22bfloat162_rn(make_float2(a4[2].x, a4[2].y));        \
        q1[1] = __float22bfloat162_rn(make_float2(a4[2].z, a4[2].w));        \
        q1[2] = __float22bfloat162_rn(make_float2(a4[3].x, a4[3].y));        \
        q1[3] = __float22bfloat162_rn(make_float2(a4[3].z, a4[3].w));        \
        *(uint4*)&As[slot][lrow * SSTR + lk] = u0;                           \
        *(uint4*)&As[slot][lrow * SSTR + lk + 8] = u1;                       \
    }

    const int nK = DD / 32;  // 16
    LDA(0);
    STA(0);
    LDA(32);
    cp16(sB, Bp, 16); cp16(sB + 16, Bp + 8, 16);
    cp_commit();

    for (int i = 0; i < nK; i++) {
        cp_wait<0>();
        __syncthreads();
        if (i + 1 < nK) {
            STA((i + 1) & 1);
            if (i + 2 < nK) { LDA((i + 2) * 32); }
            int slot = (i + 1) & 1;
            cp16(sB + slot * STGB, Bp + (i + 1) * 32, 16);
            cp16(sB + slot * STGB + 16, Bp + (i + 1) * 32 + 8, 16);
            cp_commit();
        } else {
            cp_commit();
        }
        mma_tile(sAbase + (i & 1) * STGB, sBbase + (i & 1) * STGB,
                 wm, wn, lane, acc);
    }
#undef LDA
#undef STA

#pragma unroll
    for (int mi = 0; mi < 4; mi++) {
#pragma unroll
        for (int half = 0; half < 2; half++) {
            int r = brow + wm + mi * 16 + g + half * 8;
            if (r >= M) continue;
#pragma unroll
            for (int ni = 0; ni < 4; ni++) {
                int c = bcol + wn + ni * 8 + tg * 2;
                __nv_bfloat162 h;
                h.x = __float2bfloat16_rn(acc[mi][ni][half * 2 + 0]);
                h.y = __float2bfloat16_rn(acc[mi][ni][half * 2 + 1]);
                *(__nv_bfloat162*)(C + (size_t)r * HH + c) = h;
            }
        }
    }
}

// ------- fused logits GEMM + online row LSE + diag,  K = 256 ----------------
// logits = aggl @ M2^T + cvec[col].  grid (NCHUNK=16, 32); 128 rows x 256 cols.
__global__ void k_logits_lse(const __nv_bfloat16* __restrict__ A,   // aggl [NB][256]
                             const __nv_bfloat16* __restrict__ B,   // M2   [NB][256]
                             const float* __restrict__ cv) {        // cvec [NB]
    __shared__ __align__(16) __nv_bfloat16 As[3][128 * SSTR];
    __shared__ __align__(16) __nv_bfloat16 Bs[3][128 * SSTR];
    __shared__ float red_m[4][128];
    __shared__ float red_s[4][128];

    const int tid = threadIdx.x;
    const int lane = tid & 31, warp = tid >> 5;
    const int wm = (warp & 1) * 64, wn = (warp >> 1) * 32;
    const int wnIdx = warp >> 1;
    const int g = lane >> 2, tg = lane & 3;
    const int brow = blockIdx.y * 128;
    const int chunk = blockIdx.x;

    const int lrow = tid >> 1;
    const int lk = (tid & 1) * 16;
    const __nv_bfloat16* Ap = A + (long)(brow + lrow) * HH + lk;

    uint32_t sAbase = smem_u32(&As[0][0]);
    uint32_t sBbase = smem_u32(&Bs[0][0]);
    uint32_t sA = sAbase + (lrow * SSTR + lk) * 2;
    uint32_t sB = sBbase + (lrow * SSTR + lk) * 2;

    float run_m = -3.0e38f, run_s = 0.f;  // valid for tid < 128 (row = tid)

    for (int nt = 0; nt < 2; nt++) {
        const int bcol = chunk * 256 + nt * 128;
        const __nv_bfloat16* Bp = B + (long)(bcol + lrow) * HH + lk;

        float acc[4][4][4];
#pragma unroll
        for (int a = 0; a < 4; a++)
#pragma unroll
            for (int b = 0; b < 4; b++)
#pragma unroll
                for (int c = 0; c < 4; c++) acc[a][b][c] = 0.f;

        const int nK = HH / 32;  // 8
#define ISSUE_L(k0, slot)                                                    \
    cp16(sA + (slot) * STGB, Ap + (k0), 16);                                 \
    cp16(sA + (slot) * STGB + 16, Ap + (k0) + 8, 16);                        \
    cp16(sB + (slot) * STGB, Bp + (k0), 16);                                 \
    cp16(sB + (slot) * STGB + 16, Bp + (k0) + 8, 16);
        GEMM_MAINLOOP(nK, ISSUE_L)
#undef ISSUE_L
        __syncthreads();  // mainloop reads done; also fences red_* reuse

        // ---- per warp-column local (max, sumexp) + diag, one smem round ----
        // column bias: logits[i,j] = acc + cv[j]
        float cvl[4][2];
#pragma unroll
        for (int ni = 0; ni < 4; ni++) {
            int gc = bcol + wn + ni * 8 + tg * 2;
            cvl[ni][0] = cv[gc];
            cvl[ni][1] = cv[gc + 1];
        }
#pragma unroll
        for (int mi = 0; mi < 4; mi++) {
#pragma unroll
            for (int half = 0; half < 2; half++) {
                int row = wm + mi * 16 + g + half * 8;
                float v = -3.0e38f;
#pragma unroll
                for (int ni = 0; ni < 4; ni++) {
                    v = fmaxf(v, acc[mi][ni][half * 2] + cvl[ni][0]);
                    v = fmaxf(v, acc[mi][ni][half * 2 + 1] + cvl[ni][1]);
                }
                v = fmaxf(v, __shfl_xor_sync(0xffffffffu, v, 1));
                v = fmaxf(v, __shfl_xor_sync(0xffffffffu, v, 2));
                float ps = 0.f;
#pragma unroll
                for (int ni = 0; ni < 4; ni++) {
#pragma unroll
                    for (int j = 0; j < 2; j++) {
                        float x = acc[mi][ni][half * 2 + j] + cvl[ni][j];
                        ps += __expf(x - v);
                        int gc = bcol + wn + ni * 8 + tg * 2 + j;
                        if (gc == brow + row) g_diag[gc] = x;
                    }
                }
                ps += __shfl_xor_sync(0xffffffffu, ps, 1);
                ps += __shfl_xor_sync(0xffffffffu, ps, 2);
                if (tg == 0) { red_m[wnIdx][row] = v; red_s[wnIdx][row] = ps; }
            }
        }
        __syncthreads();
        if (tid < 128) {
            float m0 = red_m[0][tid], m1 = red_m[1][tid];
            float m2 = red_m[2][tid], m3 = red_m[3][tid];
            float M = fmaxf(fmaxf(m0, m1), fmaxf(m2, m3));
            float S = red_s[0][tid] * __expf(m0 - M) + red_s[1][tid] * __expf(m1 - M)
                    + red_s[2][tid] * __expf(m2 - M) + red_s[3][tid] * __expf(m3 - M);
            float nm = fmaxf(run_m, M);
            run_s = run_s * __expf(run_m - nm) + S * __expf(M - nm);
            run_m = nm;
        }
        // no extra sync: next tile's mainloop syncs before red_* is rewritten
    }

    if (tid < 128) {
        g_pm[chunk * NB + brow + tid] = run_m;
        g_ps[chunk * NB + brow + tid] = run_s;
    }
}

// ---------- merge partials: stage 1 (32 blocks x 128 rows) ----------
__global__ void k_merge(const int* __restrict__ label) {
    __shared__ float sh[128];
    int i = blockIdx.x * 128 + threadIdx.x;
    float m = -3.0e38f;
#pragma unroll
    for (int c = 0; c < NCHUNK; c++) m = fmaxf(m, g_pm[c * NB + i]);
    float s = 0.f;
#pragma unroll
    for (int c = 0; c < NCHUNK; c++) s += g_ps[c * NB + i] * __expf(g_pm[c * NB + i] - m);
    float lse = m + logf(s);
    sh[threadIdx.x] = -(float)label[i] * (g_diag[i] - lse);
    __syncthreads();
    for (int off = 64; off > 0; off >>= 1) {
        if (threadIdx.x < off) sh[threadIdx.x] += sh[threadIdx.x + off];
        __syncthreads();
    }
    if (threadIdx.x == 0) g_part[blockIdx.x] = sh[0];
}

// ---------- stage 2: final scalar ----------
__global__ void k_final(float* __restrict__ out) {
    float v = g_part[threadIdx.x];  // 32 threads
#pragma unroll
    for (int off = 16; off > 0; off >>= 1)
        v += __shfl_xor_sync(0xffffffffu, v, off);
    if (threadIdx.x == 0) out[0] = v / (float)NB + 1.0f;  // + triplet (==1 exactly)
}

// ---------------- launch ----------------
extern "C" void kernel_launch(void* const* d_in, const int* in_sizes, int n_in,
                              void* d_out, int out_size) {
    const float* image  = (const float*)d_in[0];
    const float* xnodes = (const float*)d_in[1];
    const int*   ei     = (const int*)d_in[2];
    const int*   label  = (const int*)d_in[3];
    const float* W_img1 = (const float*)d_in[4];
    const float* b_img1 = (const float*)d_in[5];
    const float* W_img2 = (const float*)d_in[6];
    const float* b_img2 = (const float*)d_in[7];
    const float* W_g1   = (const float*)d_in[8];
    const float* b_g1   = (const float*)d_in[9];
    const float* W_g2   = (const float*)d_in[10];
    const float* b_g2   = (const float*)d_in[11];

    __nv_bfloat16 *p_ia, *p_wg1t, *p_wg2b, *p_wi1t, *p_wi2t;
    __nv_bfloat16 *p_xw1, *p_h, *p_aggl, *p_m2, *p_t1, *p_img;
    float *p_cvec;
    int *p_counts, *p_cursor;
    cudaGetSymbolAddress((void**)&p_ia, g_ia);
    cudaGetSymbolAddress((void**)&p_wg1t, g_wg1t);
    cudaGetSymbolAddress((void**)&p_wg2b, g_wg2b);
    cudaGetSymbolAddress((void**)&p_wi1t, g_wi1t);
    cudaGetSymbolAddress((void**)&p_wi2t, g_wi2t);
    cudaGetSymbolAddress((void**)&p_xw1, g_xw1);
    cudaGetSymbolAddress((void**)&p_h, g_h);
    cudaGetSymbolAddress((void**)&p_aggl, g_aggl);
    cudaGetSymbolAddress((void**)&p_m2, g_m2);
    cudaGetSymbolAddress((void**)&p_t1, g_t1);
    cudaGetSymbolAddress((void**)&p_img, g_img);
    cudaGetSymbolAddress((void**)&p_cvec, g_cvec);
    cudaGetSymbolAddress((void**)&p_counts, g_counts);
    cudaGetSymbolAddress((void**)&p_cursor, g_cursor);

    // one-time stream/event setup
    static cudaStream_t sCsr = nullptr, sMlp = nullptr;
    static cudaEvent_t evRoot, evCsr, evMlp;
    if (sCsr == nullptr) {
        cudaStreamCreateWithFlags(&sCsr, cudaStreamNonBlocking);
        cudaStreamCreateWithFlags(&sMlp, cudaStreamNonBlocking);
        cudaEventCreateWithFlags(&evRoot, cudaEventDisableTiming);
        cudaEventCreateWithFlags(&evCsr, cudaEventDisableTiming);
        cudaEventCreateWithFlags(&evMlp, cudaEventDisableTiming);
    }

    // fork point
    cudaEventRecord(evRoot, 0);

    // ---- branch 1 (sCsr): CSR build ----
    cudaStreamWaitEvent(sCsr, evRoot, 0);
    cudaMemsetAsync(p_counts, 0, NN * sizeof(int), sCsr);
    cudaMemsetAsync(p_cursor, 0, NN * sizeof(int), sCsr);
    k_count<<<(NE + 255) / 256, 256, 0, sCsr>>>(ei);
    k_scan<<<1, 1024, 0, sCsr>>>();
    k_fill<<<(NE + 255) / 256, 256, 0, sCsr>>>(ei);
    cudaEventRecord(evCsr, sCsr);

    // ---- branch 2 (sMlp): transposes + image MLP + M2 + cvec ----
    cudaStreamWaitEvent(sMlp, evRoot, 0);
    k_conv<<<(NB * DD / 4 + 255) / 256, 256, 0, sMlp>>>(image, p_ia, NB * DD);
    k_convT2<<<256, dim3(32, 32), 0, sMlp>>>(W_img1, p_wi1t, W_img2, p_wi2t);
    k_conv<<<(HH * DD / 4 + 255) / 256, 256, 0, sMlp>>>(W_g2, p_wg2b, HH * DD);
    {
        dim3 grid(HH / 128, NB / 128);
        bgemm<true, true><<<grid, 256, 0, sMlp>>>(NB, HH, DD, p_ia, p_wi1t, p_t1, b_img1);
    }
    {
        dim3 grid(DD / 128, NB / 128);
        bgemm<true, true><<<grid, 256, 0, sMlp>>>(NB, DD, HH, p_t1, p_wi2t, p_img, b_img2);
    }
    // M2 = img @ W_g2^T  (W_g2 native layout is already [N=256][K=512])
    {
        dim3 grid(HH / 128, NB / 128);
        bgemm<false, false><<<grid, 256, 0, sMlp>>>(NB, HH, DD, p_img, p_wg2b, p_m2, nullptr);
    }
    // cvec[j] = dot(b_g2, img[j])
    k_cvec<<<NB / 8, 256, 0, sMlp>>>(p_img, b_g2, p_cvec);
    cudaEventRecord(evMlp, sMlp);

    // ---- main stream: W_g1 transpose, L1 GEMM (fused convert), aggs ----
    k_convT1<<<128, dim3(32, 32)>>>(W_g1, p_wg1t);
    {
        dim3 grid(HH / 128, (NN + 127) / 128);
        bgemm_convA<<<grid, 256>>>(NN, xnodes, p_wg1t, p_xw1);
    }
    cudaStreamWaitEvent(0, evCsr, 0);
    k_aggw<true, true><<<NN, 256>>>(p_xw1, b_g1, p_h, nullptr);
    k_aggw<false, false><<<NB, 256>>>(p_h, nullptr, p_aggl, label);

    // ---- join MLP branch, then fused logits (K=256) + LSE ----
    cudaStreamWaitEvent(0, evMlp, 0);
    {
        dim3 grid(NCHUNK, NB / 128);
        k_logits_lse<<<grid, 256>>>(p_aggl, p_m2, p_cvec);
    }
    k_merge<<<32, 128>>>(label);
    k_final<<<1, 32>>>((float*)d_out);
}